// round 13
// baseline (speedup 1.0000x reference)
#include <cuda_runtime.h>
#include <cuda.h>
#include <cuda_bf16.h>
#include <cstdint>

// AssociativeLIF: x (B=32, T=128, N=4096) fp32
//   i_syn[t] = 0.5 * i_syn[t-1] + x[t]
//   v[t]     = tau * v[t-1] + (1 - tau) * i_syn[t]
//   spike[t] = (v[t] >= thr) ? 1.0f : 0.0f
//
// TMA producer/consumer pipeline: 3 stages x 8KB (STAGE_T=16).
// Replay-aware cache strategy (R7-R11 matrix):
//   - x TMA-loaded with DEFAULT L2 policy -> x (67MB) stays L2-resident
//     across graph replays (L2 = 126MB).
//   - spikes stored WRITE-THROUGH (__stwt): no L2 allocation at all, so the
//     67MB output never competes with x for L2 sets. Steady-state DRAM
//     traffic per replay collapses toward writes-only.

#define B_DIM 32
#define T_DIM 128
#define N_DIM 4096
#define NB_PER_B 32              // 4096 / 128 neurons per CTA
#define STAGE_T 16
#define NSTAGES 3
#define NITERS (T_DIM / STAGE_T) // 8
#define STAGE_BYTES (STAGE_T * 128 * 4)  // 8192
#define CONSUMERS 128
#define THREADS 160              // 4 consumer warps + 1 producer warp

// ---------------- PTX helpers ----------------
__device__ __forceinline__ uint32_t smem_u32(const void* p) {
    uint32_t a;
    asm("{ .reg .u64 t; cvta.to.shared.u64 t, %1; cvt.u32.u64 %0, t; }"
        : "=r"(a) : "l"(p));
    return a;
}

#define MBAR_INIT(addr, cnt) \
    asm volatile("mbarrier.init.shared.b64 [%0], %1;" :: "r"(addr), "r"(cnt) : "memory")

#define MBAR_EXPECT_TX(addr, bytes) \
    asm volatile("mbarrier.arrive.expect_tx.shared.b64 _, [%0], %1;" \
                 :: "r"(addr), "r"(bytes) : "memory")

#define MBAR_ARRIVE(addr) \
    asm volatile("mbarrier.arrive.shared.b64 _, [%0];" :: "r"(addr) : "memory")

#define MBAR_WAIT_ACQ(addr, ph) do {                                          \
    asm volatile(                                                             \
        "{\n\t.reg .pred P;\n\t"                                              \
        "WL_%=:\n\t"                                                          \
        "mbarrier.try_wait.parity.acquire.cta.shared::cta.b64 P, [%0], %1, 0x989680;\n\t" \
        "@P bra.uni WD_%=;\n\t"                                               \
        "bra.uni WL_%=;\n\t"                                                  \
        "WD_%=:\n\t}"                                                         \
        :: "r"(addr), "r"(ph) : "memory");                                    \
} while (0)

#define MBAR_WAIT_RELAXED(addr, ph) do {                                      \
    asm volatile(                                                             \
        "{\n\t.reg .pred P;\n\t"                                              \
        "WL_%=:\n\t"                                                          \
        "mbarrier.try_wait.parity.relaxed.cta.shared::cta.b64 P, [%0], %1, 0x989680;\n\t" \
        "@P bra.uni WD_%=;\n\t"                                               \
        "bra.uni WL_%=;\n\t"                                                  \
        "WD_%=:\n\t}"                                                         \
        :: "r"(addr), "r"(ph) : "memory");                                    \
} while (0)

// TMA load, DEFAULT L2 policy (x stays L2-resident across replays)
#define TMA_LOAD_3D(dst, map, cx, cy, cz, mbar)                               \
    asm volatile(                                                             \
        "cp.async.bulk.tensor.3d.shared::cta.global.tile.mbarrier::complete_tx::bytes " \
        "[%0], [%1, {%2, %3, %4}], [%5];"                                     \
        :: "r"(dst), "l"(map), "r"(cx), "r"(cy), "r"(cz), "r"(mbar) : "memory")

// ---------------- kernel ----------------
__global__ __launch_bounds__(THREADS)
void lif_tma_kernel(const __grid_constant__ CUtensorMap tmap,
                    const float* __restrict__ tau_mem,
                    const float* __restrict__ vthr,
                    float* __restrict__ out)
{
    __shared__ __align__(128) float buf[NSTAGES][STAGE_T][128];
    __shared__ __align__(8) unsigned long long full_bar[NSTAGES];
    __shared__ __align__(8) unsigned long long empty_bar[NSTAGES];

    const int tid = threadIdx.x;
    const int b   = blockIdx.x >> 5;            // batch index
    const int nb  = (blockIdx.x & 31) * 128;    // neuron block start

    if (tid == 0) {
        #pragma unroll
        for (int s = 0; s < NSTAGES; ++s) {
            MBAR_INIT(smem_u32(&full_bar[s]), 1);
            MBAR_INIT(smem_u32(&empty_bar[s]), 4);   // one elected arrive per consumer warp
        }
    }
    __syncthreads();

    if (tid == CONSUMERS) {
        // ---- producer (single thread of warp 4) ----
        int slot = 0, phase = 1;   // empty-wait passes immediately on first use
        #pragma unroll 1
        for (int i = 0; i < NITERS; ++i) {
            uint32_t eb = smem_u32(&empty_bar[slot]);
            uint32_t fb = smem_u32(&full_bar[slot]);
            MBAR_WAIT_RELAXED(eb, phase);
            MBAR_EXPECT_TX(fb, STAGE_BYTES);
            TMA_LOAD_3D(smem_u32(&buf[slot][0][0]), &tmap,
                        nb, i * STAGE_T, b, fb);
            if (++slot == NSTAGES) { slot = 0; phase ^= 1; }
        }
    } else if (tid < CONSUMERS) {
        // ---- consumers (warps 0-3, one thread per neuron) ----
        const int n = nb + tid;
        const int lane = tid & 31;
        const float tau = fminf(fmaxf(tau_mem[n], 0.8f), 0.98f);
        const float omt = 1.0f - tau;
        const float thr = fminf(fmaxf(vthr[n], 0.05f), 0.5f);

        float* __restrict__ op = out + (size_t)b * T_DIM * N_DIM + n;

        float isyn = 0.f;
        float v    = 0.f;

        int slot = 0, phase = 0;
        #pragma unroll 1
        for (int i = 0; i < NITERS; ++i) {
            uint32_t fb = smem_u32(&full_bar[slot]);
            MBAR_WAIT_ACQ(fb, phase);

            const int t0 = i * STAGE_T;
            #pragma unroll
            for (int tt = 0; tt < STAGE_T; ++tt) {
                float xv = buf[slot][tt][tid];
                isyn = fmaf(0.5f, isyn, xv);
                v    = fmaf(tau, v, __fmul_rn(omt, isyn));
                // WRITE-THROUGH store: no L2 allocation -> out never evicts x
                __stwt(op + (size_t)(t0 + tt) * N_DIM, (v >= thr) ? 1.0f : 0.0f);
            }

            __syncwarp();
            if (lane == 0)
                MBAR_ARRIVE(smem_u32(&empty_bar[slot]));
            if (++slot == NSTAGES) { slot = 0; phase ^= 1; }
        }
    }
}

// ---------------- host ----------------
// Hand-rolled typedef: PFN_cuTensorMapEncodeTiled is not exposed by this
// toolkit's cudaTypedefs.h. All argument types come from cuda.h.
typedef CUresult (CUDAAPI *TmaEncodeTiledFn)(
    CUtensorMap* tensorMap, CUtensorMapDataType tensorDataType,
    cuuint32_t tensorRank, void* globalAddress,
    const cuuint64_t* globalDim, const cuuint64_t* globalStrides,
    const cuuint32_t* boxDim, const cuuint32_t* elementStrides,
    CUtensorMapInterleave interleave, CUtensorMapSwizzle swizzle,
    CUtensorMapL2promotion l2Promotion, CUtensorMapFloatOOBfill oobFill);

extern "C" void kernel_launch(void* const* d_in, const int* in_sizes, int n_in,
                              void* d_out, int out_size)
{
    const float* x   = (const float*)d_in[0];
    const float* tau = (const float*)d_in[1];
    const float* thr = (const float*)d_in[2];
    float* out = (float*)d_out;

    // Tensormap for x viewed as (B, T, N) fp32:
    //   dim0 = N (4096 elems, contiguous), dim1 = T (stride 16 KB), dim2 = B.
    // Box = (128 elems, STAGE_T rows, 1).
    TmaEncodeTiledFn enc = nullptr;
    {
        void* p = nullptr;
        cudaDriverEntryPointQueryResult qr;
#if CUDART_VERSION >= 12050
        cudaGetDriverEntryPointByVersion("cuTensorMapEncodeTiled", &p, 12000,
                                         cudaEnableDefault, &qr);
#else
        cudaGetDriverEntryPoint("cuTensorMapEncodeTiled", &p,
                                cudaEnableDefault, &qr);
#endif
        enc = (TmaEncodeTiledFn)p;
    }

    CUtensorMap tmap;
    cuuint64_t dims[3]    = {N_DIM, T_DIM, B_DIM};
    cuuint64_t strides[2] = {(cuuint64_t)N_DIM * 4,
                             (cuuint64_t)N_DIM * 4 * T_DIM};
    cuuint32_t box[3]     = {128, STAGE_T, 1};
    cuuint32_t estr[3]    = {1, 1, 1};
    enc(&tmap, CU_TENSOR_MAP_DATA_TYPE_FLOAT32, 3, (void*)x,
        dims, strides, box, estr,
        CU_TENSOR_MAP_INTERLEAVE_NONE, CU_TENSOR_MAP_SWIZZLE_NONE,
        CU_TENSOR_MAP_L2_PROMOTION_L2_128B,
        CU_TENSOR_MAP_FLOAT_OOB_FILL_NONE);

    dim3 grid(B_DIM * NB_PER_B);   // 1024 CTAs
    dim3 block(THREADS);           // 160 threads
    lif_tma_kernel<<<grid, block>>>(tmap, tau, thr, out);
}

// round 14
// speedup vs baseline: 1.3959x; 1.3959x over previous
#include <cuda_runtime.h>
#include <cuda.h>
#include <cuda_bf16.h>
#include <cstdint>

// AssociativeLIF: x (B=32, T=128, N=4096) fp32
//   i_syn[t] = 0.5 * i_syn[t-1] + x[t]
//   v[t]     = tau * v[t-1] + (1 - tau) * i_syn[t]
//   spike[t] = (v[t] >= thr) ? 1.0f : 0.0f
//
// TMA pipeline + float4 consumers. Diagnosis: all prior kernels issued ~2
// scalar LSU ops per element (LDG/LDS + STG.32); the LSU dispatch floor
// (~4cyc/op) puts that at ~16us/SM -- the observed 19us invariant.
// This version: 256 neurons/CTA, each consumer thread owns 4 neurons,
// LDS.128 + STG.128 -> 0.5 LSU ops/element (4x reduction).
// Cache policy = proven winner: x TMA default (L2-resident across replays),
// spikes stored with __stcs (evict-first, never displaces x).

#define B_DIM 32
#define T_DIM 128
#define N_DIM 4096
#define NEUR_CTA 256
#define NB_PER_B (N_DIM / NEUR_CTA)      // 16
#define STAGE_T 16
#define NSTAGES 3
#define NITERS (T_DIM / STAGE_T)         // 8
#define STAGE_BYTES (STAGE_T * NEUR_CTA * 4)  // 16384
#define CONSUMERS 64                     // 2 warps, 4 neurons per thread
#define THREADS 96                       // 2 consumer warps + 1 producer warp

// ---------------- PTX helpers ----------------
__device__ __forceinline__ uint32_t smem_u32(const void* p) {
    uint32_t a;
    asm("{ .reg .u64 t; cvta.to.shared.u64 t, %1; cvt.u32.u64 %0, t; }"
        : "=r"(a) : "l"(p));
    return a;
}

#define MBAR_INIT(addr, cnt) \
    asm volatile("mbarrier.init.shared.b64 [%0], %1;" :: "r"(addr), "r"(cnt) : "memory")

#define MBAR_EXPECT_TX(addr, bytes) \
    asm volatile("mbarrier.arrive.expect_tx.shared.b64 _, [%0], %1;" \
                 :: "r"(addr), "r"(bytes) : "memory")

#define MBAR_ARRIVE(addr) \
    asm volatile("mbarrier.arrive.shared.b64 _, [%0];" :: "r"(addr) : "memory")

#define MBAR_WAIT_ACQ(addr, ph) do {                                          \
    asm volatile(                                                             \
        "{\n\t.reg .pred P;\n\t"                                              \
        "WL_%=:\n\t"                                                          \
        "mbarrier.try_wait.parity.acquire.cta.shared::cta.b64 P, [%0], %1, 0x989680;\n\t" \
        "@P bra.uni WD_%=;\n\t"                                               \
        "bra.uni WL_%=;\n\t"                                                  \
        "WD_%=:\n\t}"                                                         \
        :: "r"(addr), "r"(ph) : "memory");                                    \
} while (0)

#define MBAR_WAIT_RELAXED(addr, ph) do {                                      \
    asm volatile(                                                             \
        "{\n\t.reg .pred P;\n\t"                                              \
        "WL_%=:\n\t"                                                          \
        "mbarrier.try_wait.parity.relaxed.cta.shared::cta.b64 P, [%0], %1, 0x989680;\n\t" \
        "@P bra.uni WD_%=;\n\t"                                               \
        "bra.uni WL_%=;\n\t"                                                  \
        "WD_%=:\n\t}"                                                         \
        :: "r"(addr), "r"(ph) : "memory");                                    \
} while (0)

// TMA load, DEFAULT L2 policy (x stays L2-resident across replays)
#define TMA_LOAD_3D(dst, map, cx, cy, cz, mbar)                               \
    asm volatile(                                                             \
        "cp.async.bulk.tensor.3d.shared::cta.global.tile.mbarrier::complete_tx::bytes " \
        "[%0], [%1, {%2, %3, %4}], [%5];"                                     \
        :: "r"(dst), "l"(map), "r"(cx), "r"(cy), "r"(cz), "r"(mbar) : "memory")

// ---------------- kernel ----------------
__global__ __launch_bounds__(THREADS)
void lif_tma_kernel(const __grid_constant__ CUtensorMap tmap,
                    const float4* __restrict__ tau_mem,
                    const float4* __restrict__ vthr,
                    float* __restrict__ out)
{
    __shared__ __align__(128) float buf[NSTAGES][STAGE_T][NEUR_CTA];
    __shared__ __align__(8) unsigned long long full_bar[NSTAGES];
    __shared__ __align__(8) unsigned long long empty_bar[NSTAGES];

    const int tid = threadIdx.x;
    const int b   = blockIdx.x >> 4;                  // batch index
    const int nb  = (blockIdx.x & 15) * NEUR_CTA;     // neuron block start

    if (tid == 0) {
        #pragma unroll
        for (int s = 0; s < NSTAGES; ++s) {
            MBAR_INIT(smem_u32(&full_bar[s]), 1);
            MBAR_INIT(smem_u32(&empty_bar[s]), 2);   // one elected arrive per consumer warp
        }
    }
    __syncthreads();

    if (tid == CONSUMERS) {
        // ---- producer (single thread of warp 2) ----
        int slot = 0, phase = 1;   // empty-wait passes immediately on first use
        #pragma unroll 1
        for (int i = 0; i < NITERS; ++i) {
            uint32_t eb = smem_u32(&empty_bar[slot]);
            uint32_t fb = smem_u32(&full_bar[slot]);
            MBAR_WAIT_RELAXED(eb, phase);
            MBAR_EXPECT_TX(fb, STAGE_BYTES);
            TMA_LOAD_3D(smem_u32(&buf[slot][0][0]), &tmap,
                        nb, i * STAGE_T, b, fb);
            if (++slot == NSTAGES) { slot = 0; phase ^= 1; }
        }
    } else if (tid < CONSUMERS) {
        // ---- consumers (warps 0-1): 4 neurons per thread ----
        const int q = (nb >> 2) + tid;        // float4 index into params/out
        const int lane = tid & 31;

        float4 tm = tau_mem[q];
        float4 th = vthr[q];

        const float tax = fminf(fmaxf(tm.x, 0.8f), 0.98f);
        const float tay = fminf(fmaxf(tm.y, 0.8f), 0.98f);
        const float taz = fminf(fmaxf(tm.z, 0.8f), 0.98f);
        const float taw = fminf(fmaxf(tm.w, 0.8f), 0.98f);
        const float omx = 1.0f - tax, omy = 1.0f - tay;
        const float omz = 1.0f - taz, omw = 1.0f - taw;
        const float thx = fminf(fmaxf(th.x, 0.05f), 0.5f);
        const float thy = fminf(fmaxf(th.y, 0.05f), 0.5f);
        const float thz = fminf(fmaxf(th.z, 0.05f), 0.5f);
        const float thw = fminf(fmaxf(th.w, 0.05f), 0.5f);

        // out as float4 rows of N_DIM/4
        float4* __restrict__ op = (float4*)out + (size_t)b * T_DIM * (N_DIM / 4) + q;

        float ix = 0.f, iy = 0.f, iz = 0.f, iw = 0.f;
        float vx = 0.f, vy = 0.f, vz = 0.f, vw = 0.f;

        int slot = 0, phase = 0;
        #pragma unroll 1
        for (int i = 0; i < NITERS; ++i) {
            uint32_t fb = smem_u32(&full_bar[slot]);
            MBAR_WAIT_ACQ(fb, phase);

            const int t0 = i * STAGE_T;
            #pragma unroll
            for (int tt = 0; tt < STAGE_T; ++tt) {
                // LDS.128: warp reads 512B contiguous, conflict-free 4-phase
                float4 xv = *(const float4*)&buf[slot][tt][tid << 2];

                ix = fmaf(0.5f, ix, xv.x);
                iy = fmaf(0.5f, iy, xv.y);
                iz = fmaf(0.5f, iz, xv.z);
                iw = fmaf(0.5f, iw, xv.w);

                vx = fmaf(tax, vx, __fmul_rn(omx, ix));
                vy = fmaf(tay, vy, __fmul_rn(omy, iy));
                vz = fmaf(taz, vz, __fmul_rn(omz, iz));
                vw = fmaf(taw, vw, __fmul_rn(omw, iw));

                float4 s;
                s.x = (vx >= thx) ? 1.0f : 0.0f;
                s.y = (vy >= thy) ? 1.0f : 0.0f;
                s.z = (vz >= thz) ? 1.0f : 0.0f;
                s.w = (vw >= thw) ? 1.0f : 0.0f;
                // STG.128 evict-first: out never displaces x in L2
                __stcs(op + (size_t)(t0 + tt) * (N_DIM / 4), s);
            }

            __syncwarp();
            if (lane == 0)
                MBAR_ARRIVE(smem_u32(&empty_bar[slot]));
            if (++slot == NSTAGES) { slot = 0; phase ^= 1; }
        }
    }
}

// ---------------- host ----------------
// Hand-rolled typedef: PFN_cuTensorMapEncodeTiled is not exposed by this
// toolkit's cudaTypedefs.h. All argument types come from cuda.h.
typedef CUresult (CUDAAPI *TmaEncodeTiledFn)(
    CUtensorMap* tensorMap, CUtensorMapDataType tensorDataType,
    cuuint32_t tensorRank, void* globalAddress,
    const cuuint64_t* globalDim, const cuuint64_t* globalStrides,
    const cuuint32_t* boxDim, const cuuint32_t* elementStrides,
    CUtensorMapInterleave interleave, CUtensorMapSwizzle swizzle,
    CUtensorMapL2promotion l2Promotion, CUtensorMapFloatOOBfill oobFill);

extern "C" void kernel_launch(void* const* d_in, const int* in_sizes, int n_in,
                              void* d_out, int out_size)
{
    const float* x   = (const float*)d_in[0];
    const float4* tau = (const float4*)d_in[1];
    const float4* thr = (const float4*)d_in[2];
    float* out = (float*)d_out;

    // Tensormap for x viewed as (B, T, N) fp32:
    //   dim0 = N (4096 elems, contiguous), dim1 = T (stride 16 KB), dim2 = B.
    // Box = (NEUR_CTA elems, STAGE_T rows, 1).
    TmaEncodeTiledFn enc = nullptr;
    {
        void* p = nullptr;
        cudaDriverEntryPointQueryResult qr;
#if CUDART_VERSION >= 12050
        cudaGetDriverEntryPointByVersion("cuTensorMapEncodeTiled", &p, 12000,
                                         cudaEnableDefault, &qr);
#else
        cudaGetDriverEntryPoint("cuTensorMapEncodeTiled", &p,
                                cudaEnableDefault, &qr);
#endif
        enc = (TmaEncodeTiledFn)p;
    }

    CUtensorMap tmap;
    cuuint64_t dims[3]    = {N_DIM, T_DIM, B_DIM};
    cuuint64_t strides[2] = {(cuuint64_t)N_DIM * 4,
                             (cuuint64_t)N_DIM * 4 * T_DIM};
    cuuint32_t box[3]     = {NEUR_CTA, STAGE_T, 1};
    cuuint32_t estr[3]    = {1, 1, 1};
    enc(&tmap, CU_TENSOR_MAP_DATA_TYPE_FLOAT32, 3, (void*)x,
        dims, strides, box, estr,
        CU_TENSOR_MAP_INTERLEAVE_NONE, CU_TENSOR_MAP_SWIZZLE_NONE,
        CU_TENSOR_MAP_L2_PROMOTION_L2_128B,
        CU_TENSOR_MAP_FLOAT_OOB_FILL_NONE);

    dim3 grid(B_DIM * NB_PER_B);   // 512 CTAs
    dim3 block(THREADS);           // 96 threads
    lif_tma_kernel<<<grid, block>>>(tmap, tau, thr, out);
}